// round 15
// baseline (speedup 1.0000x reference)
#include <cuda_runtime.h>
#include <cuda_fp16.h>
#include <cstdint>

// Problem constants
#define Bc   2
#define Sc   2048
#define Dc   1024
#define Hc   16
#define HDc  64
#define Wc   128

// Scratch (allocation-free rule: __device__ globals). All fp16 fragments,
// stored as u32 words (2 halves each).
__device__ unsigned g_xperm[Bc * Sc * Dc / 2];     // x, A-frag layout
__device__ unsigned g_attnperm[Bc * Sc * Dc / 2];  // attn out, A-frag layout
__device__ unsigned g_wqkvperm[3 * Dc * Dc / 2];   // in_proj_w, B-frag layout
__device__ unsigned g_woutperm[Dc * Dc / 2];       // out_proj_w, B-frag layout
// Attention fragment buffers: per (b,h,tile64) block = 2048 words (8KB)
__device__ unsigned g_qfh[Bc * Hc * 32 * 2048];    // Q A-frag hi (scaled)
__device__ unsigned g_qfl[Bc * Hc * 32 * 2048];    // Q A-frag lo
__device__ unsigned g_kfh[Bc * Hc * 32 * 2048];    // K B-frag hi
__device__ unsigned g_kfl[Bc * Hc * 32 * 2048];    // K B-frag lo
__device__ unsigned g_vf [Bc * Hc * 32 * 2048];    // V^T B-frag (n=dim,k=key)

__device__ __forceinline__ unsigned h2(float a, float b) {
    __half2 t = __floats2half2_rn(a, b);
    return *reinterpret_cast<unsigned*>(&t);
}
__device__ __forceinline__ float hi16(float x) {
    return __half2float(__float2half_rn(x));
}

__device__ __forceinline__ void mma16(float* c, unsigned a0, unsigned a1,
                                      unsigned a2, unsigned a3,
                                      unsigned b0, unsigned b1) {
    asm volatile(
        "mma.sync.aligned.m16n8k16.row.col.f32.f16.f16.f32 "
        "{%0,%1,%2,%3}, {%4,%5,%6,%7}, {%8,%9}, {%0,%1,%2,%3};\n"
        : "+f"(c[0]), "+f"(c[1]), "+f"(c[2]), "+f"(c[3])
        : "r"(a0), "r"(a1), "r"(a2), "r"(a3), "r"(b0), "r"(b1));
}

// ---------------------------------------------------------------------------
// fp16 operand packers (unchanged, proven).
// ---------------------------------------------------------------------------
__global__ __launch_bounds__(256) void permA_h(
    const float* __restrict__ X, unsigned* __restrict__ P, int M, int K)
{
    int idx = blockIdx.x * 256 + threadIdx.x;
    if (idx >= (M * K) >> 1) return;
    int slot = idx & 3;
    int lane = (idx >> 2) & 31;
    int mtg  = (idx >> 7) & 7;
    int kstep = (idx >> 10) & 1;
    int rest = idx >> 11;
    int nKB = K >> 5;
    int kblk = rest % nKB, mblk = rest / nKB;
    int r = mblk * 128 + mtg * 16 + (slot & 1) * 8 + (lane >> 2);
    int d = kblk * 32 + kstep * 16 + ((slot >> 1) & 1) * 8 + 2 * (lane & 3);
    const float* x = X + (size_t)r * K + d;
    P[idx] = h2(x[0], x[1]);
}

__global__ __launch_bounds__(256) void permB_h(
    const float* __restrict__ X, unsigned* __restrict__ P, int N, int K)
{
    int idx = blockIdx.x * 256 + threadIdx.x;
    if (idx >= (N * K) >> 1) return;
    int slot = idx & 3;
    int lane = (idx >> 2) & 31;
    int ntp  = (idx >> 7) & 7;
    int kstep = (idx >> 10) & 1;
    int rest = idx >> 11;
    int nKB = K >> 5;
    int kblk = rest % nKB, nblk = rest / nKB;
    int e = (slot >> 1) & 1, kb = slot & 1;
    int n = nblk * 128 + ntp * 16 + e * 8 + (lane >> 2);
    int d = kblk * 32 + kstep * 16 + kb * 8 + 2 * (lane & 3);
    const float* x = X + (size_t)n * K + d;
    P[idx] = h2(x[0], x[1]);
}

// ---------------------------------------------------------------------------
// fp16 GEMM mainloop: 128x128 CTA tile, 4 warps (2x2), 64x64 warp tiles.
// K-tile 64 (4 k16 steps, 128 HMMA/warp per barrier), 3-stage cp.async
// (32KB/stage, 96KB total -> 2 CTAs/SM).
// ---------------------------------------------------------------------------
#define GSTAGES 3

#define ISSUE_TILE(t)                                                          \
    {                                                                          \
        uint32_t st = sbase + ((t) % GSTAGES) * 32768u;                        \
        const unsigned* asrc = Atile + (size_t)(t) * 4096;                     \
        const unsigned* bsrc = Btile + (size_t)(t) * 4096;                     \
        _Pragma("unroll")                                                      \
        for (int j = 0; j < 8; j++) {                                          \
            int c = tid + 128 * j;                                             \
            asm volatile("cp.async.cg.shared.global [%0],[%1],16;\n"           \
                         :: "r"(st + c * 16u), "l"(asrc + c * 4));             \
            asm volatile("cp.async.cg.shared.global [%0],[%1],16;\n"           \
                         :: "r"(st + 16384u + c * 16u), "l"(bsrc + c * 4));    \
        }                                                                      \
        asm volatile("cp.async.commit_group;\n");                              \
    }

#define GEMM_MAINLOOP(Ap_, Bp_, nKB_)                                          \
    float acc[4][8][4];                                                        \
    _Pragma("unroll")                                                          \
    for (int i = 0; i < 4; i++)                                                \
        _Pragma("unroll")                                                      \
        for (int j = 0; j < 8; j++)                                            \
            _Pragma("unroll")                                                  \
            for (int c = 0; c < 4; c++) acc[i][j][c] = 0.f;                    \
    const unsigned* Atile = (Ap_) + (size_t)blockIdx.y * (nKB_) * 4096;        \
    const unsigned* Btile = (Bp_) + (size_t)blockIdx.x * (nKB_) * 4096;        \
    const uint32_t sbase = (uint32_t)__cvta_generic_to_shared(smg);            \
    ISSUE_TILE(0);                                                             \
    ISSUE_TILE(1);                                                             \
    for (int t = 0; t < (nKB_); t++) {                                         \
        asm volatile("cp.async.wait_group 1;\n");                              \
        __syncthreads();                                                       \
        if (t + 2 < (nKB_)) { ISSUE_TILE(t + 2); }                             \
        else { asm volatile("cp.async.commit_group;\n"); }                     \
        const unsigned* sA = smg + (t % GSTAGES) * 8192;                       \
        const unsigned* sB = sA + 4096;                                        \
        _Pragma("unroll")                                                      \
        for (int ks = 0; ks < 4; ks++) {                                       \
            const int lx = lane << 2;                                          \
            uint4 af[4], bf[4];                                                \
            _Pragma("unroll")                                                  \
            for (int mt = 0; mt < 4; mt++)                                     \
                af[mt] = *(const uint4*)&sA[ks * 1024 + (warp_m * 4 + mt) * 128 + lx]; \
            _Pragma("unroll")                                                  \
            for (int p = 0; p < 4; p++)                                        \
                bf[p] = *(const uint4*)&sB[ks * 1024 + (warp_n * 4 + p) * 128 + lx]; \
            _Pragma("unroll")                                                  \
            for (int mt = 0; mt < 4; mt++) {                                   \
                _Pragma("unroll")                                              \
                for (int nt = 0; nt < 8; nt++) {                               \
                    const uint4& b4 = bf[nt >> 1];                             \
                    unsigned b0 = (nt & 1) ? b4.z : b4.x;                      \
                    unsigned b1 = (nt & 1) ? b4.w : b4.y;                      \
                    mma16(acc[mt][nt], af[mt].x, af[mt].y, af[mt].z, af[mt].w, b0, b1); \
                }                                                              \
            }                                                                  \
        }                                                                      \
    }

// ---------------------------------------------------------------------------
// Out-projection GEMM: row-major fp32 C + bias.
// ---------------------------------------------------------------------------
__global__ __launch_bounds__(128, 2) void gemm_h(
    const unsigned* __restrict__ Ap, const unsigned* __restrict__ Bp,
    const float* __restrict__ bias, float* __restrict__ C,
    int M, int N, int K)
{
    extern __shared__ unsigned smg[];
    const int tid    = threadIdx.x;
    const int lane   = tid & 31;
    const int wid    = tid >> 5;
    const int warp_m = wid >> 1;
    const int warp_n = wid & 1;
    const int nKB    = K >> 6;

    GEMM_MAINLOOP(Ap, Bp, nKB)

    const int m0 = blockIdx.y * 128;
    const int n0 = blockIdx.x * 128;
#pragma unroll
    for (int mt = 0; mt < 4; mt++) {
        int row = m0 + warp_m * 64 + mt * 16 + (lane >> 2);
#pragma unroll
        for (int nt = 0; nt < 8; nt++) {
            int col = n0 + warp_n * 64 + nt * 8 + 2 * (lane & 3);
            float2 bv = *(const float2*)&bias[col];
            float2 o0 = make_float2(acc[mt][nt][0] + bv.x, acc[mt][nt][1] + bv.y);
            float2 o1 = make_float2(acc[mt][nt][2] + bv.x, acc[mt][nt][3] + bv.y);
            *(float2*)&C[(size_t)row * N + col]       = o0;
            *(float2*)&C[(size_t)(row + 8) * N + col] = o1;
        }
    }
}

// ---------------------------------------------------------------------------
// QKV GEMM with fused fp16 fragment-pack epilogue.
// Grid.x: 0-7 Q, 8-15 K, 16-23 V (128-col bands).
// ---------------------------------------------------------------------------
__global__ __launch_bounds__(128, 2) void gemm_qkv(
    const unsigned* __restrict__ Ap, const unsigned* __restrict__ Bp,
    const float* __restrict__ bias)
{
    extern __shared__ unsigned smg[];
    const int tid    = threadIdx.x;
    const int lane   = tid & 31;
    const int wid    = tid >> 5;
    const int warp_m = wid >> 1;
    const int warp_n = wid & 1;
    const int nKB    = Dc >> 6;

    GEMM_MAINLOOP(Ap, Bp, nKB)

    const int m0 = blockIdx.y * 128;
    const int n0 = blockIdx.x * 128;
    const int kind = n0 >> 10;    // 0=Q, 1=K, 2=V
    __half* gv = (__half*)g_vf;

#pragma unroll
    for (int mt = 0; mt < 4; mt++) {
        int row = m0 + warp_m * 64 + mt * 16 + (lane >> 2);
#pragma unroll
        for (int nt = 0; nt < 8; nt++) {
            int col = n0 + warp_n * 64 + nt * 8 + 2 * (lane & 3);
            float2 bv = *(const float2*)&bias[col];
            float v0 = acc[mt][nt][0] + bv.x, v1 = acc[mt][nt][1] + bv.y;
            float v2 = acc[mt][nt][2] + bv.x, v3 = acc[mt][nt][3] + bv.y;

            int s = row & (Sc - 1), b = row >> 11;
            int cc = col & 1023;
            int h = cc >> 6, d = cc & 63;           // d even
            int sl = s & 63;
            size_t base = ((size_t)(b * Hc + h) * 32 + (s >> 6)) * 2048;

            if (kind == 0) {
                float q0 = v0 * 0.125f, q1 = v1 * 0.125f;
                float q2 = v2 * 0.125f, q3 = v3 * 0.125f;
                int idx = (d >> 4) * 512 + ((sl >> 4) & 3) * 128
                        + (((sl & 7) << 2) | ((d >> 1) & 3)) * 4
                        + (((d >> 3) & 1) << 1);
                g_qfh[base + idx]     = h2(q0, q1);
                g_qfh[base + idx + 1] = h2(q2, q3);
                g_qfl[base + idx]     = h2(q0 - hi16(q0), q1 - hi16(q1));
                g_qfl[base + idx + 1] = h2(q2 - hi16(q2), q3 - hi16(q3));
            } else if (kind == 1) {
                int idx = (d >> 4) * 512 + ((sl >> 4) & 3) * 128
                        + (((sl & 7) << 2) | ((d >> 1) & 3)) * 4
                        + ((d >> 3) & 1);
                g_kfh[base + idx]     = h2(v0, v1);       // e=0 (row s)
                g_kfh[base + idx + 2] = h2(v2, v3);       // e=1 (row s+8)
                g_kfl[base + idx]     = h2(v0 - hi16(v0), v1 - hi16(v1));
                g_kfl[base + idx + 2] = h2(v2 - hi16(v2), v3 - hi16(v3));
            } else {
                float vv[4] = {v0, v1, v2, v3};
#pragma unroll
                for (int e = 0; e < 4; e++) {
                    int key = sl + (e >> 1) * 8;
                    int dim = d + (e & 1);
                    int widx = (key >> 4) * 512 + ((dim >> 4) & 3) * 128
                             + (((dim & 7) << 2) | ((key >> 1) & 3)) * 4
                             + ((((dim >> 3) & 1) << 1) | ((key >> 3) & 1));
                    gv[(base + widx) * 2 + (key & 1)] = __float2half_rn(vv[e]);
                }
            }
        }
    }
}

// ---------------------------------------------------------------------------
// fp16 tensor-core windowed attention (unchanged from R13, proven).
// ---------------------------------------------------------------------------
__global__ __launch_bounds__(128, 3) void attn_mma(unsigned* __restrict__ Operm)
{
    extern __shared__ unsigned sm[];
    const int tid = threadIdx.x, lane = tid & 31, wid = tid >> 5;
    const int qt = blockIdx.x, h = blockIdx.y, b = blockIdx.z;
    const int bh = b * Hc + h;
    const uint32_t sbase = (uint32_t)__cvta_generic_to_shared(sm);

    {
        const unsigned* qh_ = g_qfh + ((size_t)bh * 32 + qt) * 2048;
        const unsigned* ql_ = g_qfl + ((size_t)bh * 32 + qt) * 2048;
#pragma unroll
        for (int j = 0; j < 4; j++) {
            int c = tid + 128 * j;
            asm volatile("cp.async.cg.shared.global [%0],[%1],16;"
                         :: "r"(sbase + c * 16u), "l"(qh_ + c * 4));
            asm volatile("cp.async.cg.shared.global [%0],[%1],16;"
                         :: "r"(sbase + 8192u + c * 16u), "l"(ql_ + c * 4));
        }
        asm volatile("cp.async.commit_group;");
        asm volatile("cp.async.wait_group 0;");
    }
    __syncthreads();
    uint4 qh[4], ql[4];
#pragma unroll
    for (int ks = 0; ks < 4; ks++) {
        qh[ks] = *(const uint4*)&sm[ks * 512 + wid * 128 + lane * 4];
        ql[ks] = *(const uint4*)&sm[2048 + ks * 512 + wid * 128 + lane * 4];
    }
    __syncthreads();

    const int ktlo = (qt - 2 > 0) ? qt - 2 : 0;
    const int kthi = (qt + 2 < 31) ? qt + 2 : 31;
    const int nT = kthi - ktlo + 1;

#define ISSUE_KV(kt, p)                                                         \
    {                                                                           \
        const unsigned* kh_ = g_kfh + ((size_t)bh * 32 + (kt)) * 2048;          \
        const unsigned* kl_ = g_kfl + ((size_t)bh * 32 + (kt)) * 2048;          \
        const unsigned* v_  = g_vf  + ((size_t)bh * 32 + (kt)) * 2048;          \
        uint32_t dst = sbase + (p) * 24576u;                                    \
        _Pragma("unroll")                                                       \
        for (int j = 0; j < 4; j++) {                                           \
            int c = tid + 128 * j;                                              \
            asm volatile("cp.async.cg.shared.global [%0],[%1],16;"              \
                         :: "r"(dst + c * 16u), "l"(kh_ + c * 4));              \
            asm volatile("cp.async.cg.shared.global [%0],[%1],16;"              \
                         :: "r"(dst + 8192u + c * 16u), "l"(kl_ + c * 4));      \
            asm volatile("cp.async.cg.shared.global [%0],[%1],16;"              \
                         :: "r"(dst + 16384u + c * 16u), "l"(v_ + c * 4));      \
        }                                                                       \
        asm volatile("cp.async.commit_group;");                                 \
    }

    ISSUE_KV(ktlo, 0);
    ISSUE_KV(ktlo + 1, 1);

    float o[8][4];
#pragma unroll
    for (int i = 0; i < 8; i++)
#pragma unroll
        for (int c = 0; c < 4; c++) o[i][c] = 0.f;
    float mA = -1e30f, mB = -1e30f, lA = 0.f, lB = 0.f;

    for (int j = 0; j < nT; j++) {
        const int kt = ktlo + j, p = j & 1;
        asm volatile("cp.async.wait_group 1;");
        __syncthreads();

        const unsigned* bKh = sm + p * 6144;
        const unsigned* bKl = bKh + 2048;
        const unsigned* bV  = bKh + 4096;

        float s[8][4];
#pragma unroll
        for (int i = 0; i < 8; i++)
#pragma unroll
            for (int c = 0; c < 4; c++) s[i][c] = 0.f;

#pragma unroll
        for (int ks = 0; ks < 4; ks++) {
            uint4 kh4[4], kl4[4];
#pragma unroll
            for (int ntp = 0; ntp < 4; ntp++) {
                kh4[ntp] = *(const uint4*)&bKh[ks * 512 + ntp * 128 + lane * 4];
                kl4[ntp] = *(const uint4*)&bKl[ks * 512 + ntp * 128 + lane * 4];
            }
#pragma unroll
            for (int ntp = 0; ntp < 4; ntp++) {
#pragma unroll
                for (int e = 0; e < 2; e++) {
                    unsigned bh0 = e ? kh4[ntp].z : kh4[ntp].x;
                    unsigned bh1 = e ? kh4[ntp].w : kh4[ntp].y;
                    unsigned bl0 = e ? kl4[ntp].z : kl4[ntp].x;
                    unsigned bl1 = e ? kl4[ntp].w : kl4[ntp].y;
                    float* c = s[ntp * 2 + e];
                    mma16(c, qh[ks].x, qh[ks].y, qh[ks].z, qh[ks].w, bh0, bh1);
                    mma16(c, ql[ks].x, ql[ks].y, ql[ks].z, ql[ks].w, bh0, bh1);
                    mma16(c, qh[ks].x, qh[ks].y, qh[ks].z, qh[ks].w, bl0, bl1);
                }
            }
        }

        if (kt - qt == 2 || qt - kt == 2) {
            int q1 = qt * 64 + wid * 16 + (lane >> 2);
            int k00 = kt * 64 + 2 * (lane & 3);
#pragma unroll
            for (int nt = 0; nt < 8; nt++) {
#pragma unroll
                for (int ci = 0; ci < 4; ci++) {
                    int qv = q1 + ((ci >= 2) ? 8 : 0);
                    int kv = k00 + nt * 8 + (ci & 1);
                    int d = qv - kv; d = (d < 0) ? -d : d;
                    if (d > Wc) s[nt][ci] = -1e30f;
                }
            }
        }

        float tA = -1e30f, tB = -1e30f;
#pragma unroll
        for (int nt = 0; nt < 8; nt++) {
            tA = fmaxf(tA, fmaxf(s[nt][0], s[nt][1]));
            tB = fmaxf(tB, fmaxf(s[nt][2], s[nt][3]));
        }
        tA = fmaxf(tA, __shfl_xor_sync(0xffffffffu, tA, 1));
        tA = fmaxf(tA, __shfl_xor_sync(0xffffffffu, tA, 2));
        tB = fmaxf(tB, __shfl_xor_sync(0xffffffffu, tB, 1));
        tB = fmaxf(tB, __shfl_xor_sync(0xffffffffu, tB, 2));
        float mnA = fmaxf(mA, tA), mnB = fmaxf(mB, tB);
        float aA = __expf(mA - mnA), aB = __expf(mB - mnB);
        mA = mnA; mB = mnB;
        float sumA = 0.f, sumB = 0.f;
#pragma unroll
        for (int nt = 0; nt < 8; nt++) {
            s[nt][0] = __expf(s[nt][0] - mnA);
            s[nt][1] = __expf(s[nt][1] - mnA);
            s[nt][2] = __expf(s[nt][2] - mnB);
            s[nt][3] = __expf(s[nt][3] - mnB);
            sumA += s[nt][0] + s[nt][1];
            sumB += s[nt][2] + s[nt][3];
        }
        sumA += __shfl_xor_sync(0xffffffffu, sumA, 1);
        sumA += __shfl_xor_sync(0xffffffffu, sumA, 2);
        sumB += __shfl_xor_sync(0xffffffffu, sumB, 1);
        sumB += __shfl_xor_sync(0xffffffffu, sumB, 2);
        lA = lA * aA + sumA;
        lB = lB * aB + sumB;
#pragma unroll
        for (int nt = 0; nt < 8; nt++) {
            o[nt][0] *= aA; o[nt][1] *= aA;
            o[nt][2] *= aB; o[nt][3] *= aB;
        }

#pragma unroll
        for (int kk = 0; kk < 4; kk++) {
            unsigned pa0 = h2(s[2 * kk][0],     s[2 * kk][1]);
            unsigned pa1 = h2(s[2 * kk][2],     s[2 * kk][3]);
            unsigned pa2 = h2(s[2 * kk + 1][0], s[2 * kk + 1][1]);
            unsigned pa3 = h2(s[2 * kk + 1][2], s[2 * kk + 1][3]);
            uint4 v4[4];
#pragma unroll
            for (int ntp = 0; ntp < 4; ntp++)
                v4[ntp] = *(const uint4*)&bV[kk * 512 + ntp * 128 + lane * 4];
#pragma unroll
            for (int ntp = 0; ntp < 4; ntp++) {
#pragma unroll
                for (int e = 0; e < 2; e++) {
                    unsigned b0 = e ? v4[ntp].z : v4[ntp].x;
                    unsigned b1 = e ? v4[ntp].w : v4[ntp].y;
                    mma16(o[ntp * 2 + e], pa0, pa1, pa2, pa3, b0, b1);
                }
            }
        }
        __syncthreads();

        if (kt + 2 <= kthi) {
            ISSUE_KV(kt + 2, p);
        } else {
            asm volatile("cp.async.commit_group;");
        }
    }

    float iA = 1.f / lA, iB = 1.f / lB;
    int q = b * Sc + qt * 64 + wid * 16 + (lane >> 2);
    int mblk = q >> 7, mtg = (q >> 4) & 7;
#pragma unroll
    for (int nt = 0; nt < 8; nt++) {
        int c0 = h * 64 + nt * 8 + 2 * (lane & 3);
        int kblk = c0 >> 5;
        int kstep = (c0 >> 4) & 1;
        int lanep = ((q & 7) << 2) | ((c0 >> 1) & 3);
        int slotb = ((c0 >> 3) & 1) << 1;
        size_t bidx = (size_t)(mblk * 32 + kblk) * 2048 + kstep * 1024
                    + mtg * 128 + lanep * 4 + slotb;
        Operm[bidx]     = h2(o[nt][0] * iA, o[nt][1] * iA);
        Operm[bidx + 1] = h2(o[nt][2] * iB, o[nt][3] * iB);
    }
#undef ISSUE_KV
}

// ---------------------------------------------------------------------------
extern "C" void kernel_launch(void* const* d_in, const int* in_sizes, int n_in,
                              void* d_out, int out_size)
{
    (void)in_sizes; (void)n_in; (void)out_size;
    const float* x     = (const float*)d_in[0];
    const float* in_w  = (const float*)d_in[1];
    const float* in_b  = (const float*)d_in[2];
    const float* out_w = (const float*)d_in[3];
    const float* out_b = (const float*)d_in[4];
    float* out = (float*)d_out;

    unsigned *xp, *ap, *wqp, *wop;
    cudaGetSymbolAddress((void**)&xp,  g_xperm);
    cudaGetSymbolAddress((void**)&ap,  g_attnperm);
    cudaGetSymbolAddress((void**)&wqp, g_wqkvperm);
    cudaGetSymbolAddress((void**)&wop, g_woutperm);

    const int M = Bc * Sc;                      // 4096
    const int smem_gemm = GSTAGES * 32768;      // 96 KB -> 2 CTAs/SM
    const int smem_attn = 12288 * 4;            // 48 KB -> 3 CTAs/SM
    cudaFuncSetAttribute(gemm_h,
                         cudaFuncAttributeMaxDynamicSharedMemorySize, smem_gemm);
    cudaFuncSetAttribute(gemm_qkv,
                         cudaFuncAttributeMaxDynamicSharedMemorySize, smem_gemm);
    cudaFuncSetAttribute(attn_mma,
                         cudaFuncAttributeMaxDynamicSharedMemorySize, smem_attn);

    // Operand packers (fp16)
    permA_h<<<(M * Dc / 2 + 255) / 256, 256>>>(x, xp, M, Dc);
    permB_h<<<(3 * Dc * Dc / 2 + 255) / 256, 256>>>(in_w, wqp, 3 * Dc, Dc);
    permB_h<<<(Dc * Dc / 2 + 255) / 256, 256>>>(out_w, wop, Dc, Dc);

    // 1) QKV projection with fused Q/K/V fragment-pack epilogue
    gemm_qkv<<<dim3(3 * Dc / 128, M / 128), 128, smem_gemm>>>(xp, wqp, in_b);

    // 2) fp16 tensor-core attention (writes out-proj A-fragments directly)
    attn_mma<<<dim3(Sc / 64, Hc, Bc), 128, smem_attn>>>(ap);

    // 3) Output projection
    gemm_h<<<dim3(Dc / 128, M / 128), 128, smem_gemm>>>(
        ap, wop, out_b, out, M, Dc, Dc);
}

// round 17
// speedup vs baseline: 1.5135x; 1.5135x over previous
#include <cuda_runtime.h>
#include <cuda_fp16.h>
#include <cstdint>

// Problem constants
#define Bc   2
#define Sc   2048
#define Dc   1024
#define Hc   16
#define HDc  64
#define Wc   128

// Scratch (allocation-free rule: __device__ globals). All fp16 fragments,
// stored as u32 words (2 halves each).
__device__ unsigned g_xperm[Bc * Sc * Dc / 2];     // x, A-frag layout
__device__ unsigned g_attnperm[Bc * Sc * Dc / 2];  // attn out, A-frag layout
__device__ unsigned g_wqkvperm[3 * Dc * Dc / 2];   // in_proj_w, B-frag layout
__device__ unsigned g_woutperm[Dc * Dc / 2];       // out_proj_w, B-frag layout
// Attention fragment buffers: per (b,h,tile64) block = 2048 words (8KB)
__device__ unsigned g_qfh[Bc * Hc * 32 * 2048];    // Q A-frag hi (scaled)
__device__ unsigned g_qfl[Bc * Hc * 32 * 2048];    // Q A-frag lo
__device__ unsigned g_kfh[Bc * Hc * 32 * 2048];    // K B-frag hi
__device__ unsigned g_kfl[Bc * Hc * 32 * 2048];    // K B-frag lo
__device__ unsigned g_vf [Bc * Hc * 32 * 2048];    // V^T B-frag (n=dim,k=key)

__device__ __forceinline__ unsigned h2(float a, float b) {
    __half2 t = __floats2half2_rn(a, b);
    return *reinterpret_cast<unsigned*>(&t);
}
__device__ __forceinline__ float hi16(float x) {
    return __half2float(__float2half_rn(x));
}

__device__ __forceinline__ void mma16(float* c, unsigned a0, unsigned a1,
                                      unsigned a2, unsigned a3,
                                      unsigned b0, unsigned b1) {
    asm volatile(
        "mma.sync.aligned.m16n8k16.row.col.f32.f16.f16.f32 "
        "{%0,%1,%2,%3}, {%4,%5,%6,%7}, {%8,%9}, {%0,%1,%2,%3};\n"
        : "+f"(c[0]), "+f"(c[1]), "+f"(c[2]), "+f"(c[3])
        : "r"(a0), "r"(a1), "r"(a2), "r"(a3), "r"(b0), "r"(b1));
}

// ---------------------------------------------------------------------------
// fp16 operand packers (unchanged, proven).
// ---------------------------------------------------------------------------
__global__ __launch_bounds__(256) void permA_h(
    const float* __restrict__ X, unsigned* __restrict__ P, int M, int K)
{
    int idx = blockIdx.x * 256 + threadIdx.x;
    if (idx >= (M * K) >> 1) return;
    int slot = idx & 3;
    int lane = (idx >> 2) & 31;
    int mtg  = (idx >> 7) & 7;
    int kstep = (idx >> 10) & 1;
    int rest = idx >> 11;
    int nKB = K >> 5;
    int kblk = rest % nKB, mblk = rest / nKB;
    int r = mblk * 128 + mtg * 16 + (slot & 1) * 8 + (lane >> 2);
    int d = kblk * 32 + kstep * 16 + ((slot >> 1) & 1) * 8 + 2 * (lane & 3);
    const float* x = X + (size_t)r * K + d;
    P[idx] = h2(x[0], x[1]);
}

__global__ __launch_bounds__(256) void permB_h(
    const float* __restrict__ X, unsigned* __restrict__ P, int N, int K)
{
    int idx = blockIdx.x * 256 + threadIdx.x;
    if (idx >= (N * K) >> 1) return;
    int slot = idx & 3;
    int lane = (idx >> 2) & 31;
    int ntp  = (idx >> 7) & 7;
    int kstep = (idx >> 10) & 1;
    int rest = idx >> 11;
    int nKB = K >> 5;
    int kblk = rest % nKB, nblk = rest / nKB;
    int e = (slot >> 1) & 1, kb = slot & 1;
    int n = nblk * 128 + ntp * 16 + e * 8 + (lane >> 2);
    int d = kblk * 32 + kstep * 16 + kb * 8 + 2 * (lane & 3);
    const float* x = X + (size_t)n * K + d;
    P[idx] = h2(x[0], x[1]);
}

// ---------------------------------------------------------------------------
// fp16 GEMM mainloop: 128x128 CTA tile, 4 warps (2x2), 64x64 warp tiles.
// K-tile 32 (R14 proven), 5-stage cp.async (16KB/stage, 80KB -> 2 CTAs/SM),
// wait_group 3: 3 tiles (48KB) in flight while consuming.
// ---------------------------------------------------------------------------
#define GSTAGES 5

#define ISSUE_TILE(t)                                                          \
    {                                                                          \
        uint32_t st = sbase + ((t) % GSTAGES) * 16384u;                        \
        const unsigned* asrc = Atile + (size_t)(t) * 2048;                     \
        const unsigned* bsrc = Btile + (size_t)(t) * 2048;                     \
        _Pragma("unroll")                                                      \
        for (int j = 0; j < 4; j++) {                                          \
            int c = tid + 128 * j;                                             \
            asm volatile("cp.async.cg.shared.global [%0],[%1],16;\n"           \
                         :: "r"(st + c * 16u), "l"(asrc + c * 4));             \
            asm volatile("cp.async.cg.shared.global [%0],[%1],16;\n"           \
                         :: "r"(st + 8192u + c * 16u), "l"(bsrc + c * 4));     \
        }                                                                      \
        asm volatile("cp.async.commit_group;\n");                              \
    }

#define GEMM_MAINLOOP(Ap_, Bp_, nKB_)                                          \
    float acc[4][8][4];                                                        \
    _Pragma("unroll")                                                          \
    for (int i = 0; i < 4; i++)                                                \
        _Pragma("unroll")                                                      \
        for (int j = 0; j < 8; j++)                                            \
            _Pragma("unroll")                                                  \
            for (int c = 0; c < 4; c++) acc[i][j][c] = 0.f;                    \
    const unsigned* Atile = (Ap_) + (size_t)blockIdx.y * (nKB_) * 2048;        \
    const unsigned* Btile = (Bp_) + (size_t)blockIdx.x * (nKB_) * 2048;        \
    const uint32_t sbase = (uint32_t)__cvta_generic_to_shared(smg);            \
    ISSUE_TILE(0);                                                             \
    ISSUE_TILE(1);                                                             \
    ISSUE_TILE(2);                                                             \
    ISSUE_TILE(3);                                                             \
    for (int t = 0; t < (nKB_); t++) {                                         \
        asm volatile("cp.async.wait_group 3;\n");                              \
        __syncthreads();                                                       \
        if (t + 4 < (nKB_)) { ISSUE_TILE(t + 4); }                             \
        else { asm volatile("cp.async.commit_group;\n"); }                     \
        const unsigned* sA = smg + (t % GSTAGES) * 4096;                       \
        const unsigned* sB = sA + 2048;                                        \
        _Pragma("unroll")                                                      \
        for (int ks = 0; ks < 2; ks++) {                                       \
            const int lx = lane << 2;                                          \
            uint4 af[4], bf[4];                                                \
            _Pragma("unroll")                                                  \
            for (int mt = 0; mt < 4; mt++)                                     \
                af[mt] = *(const uint4*)&sA[ks * 1024 + (warp_m * 4 + mt) * 128 + lx]; \
            _Pragma("unroll")                                                  \
            for (int p = 0; p < 4; p++)                                        \
                bf[p] = *(const uint4*)&sB[ks * 1024 + (warp_n * 4 + p) * 128 + lx]; \
            _Pragma("unroll")                                                  \
            for (int mt = 0; mt < 4; mt++) {                                   \
                _Pragma("unroll")                                              \
                for (int nt = 0; nt < 8; nt++) {                               \
                    const uint4& b4 = bf[nt >> 1];                             \
                    unsigned b0 = (nt & 1) ? b4.z : b4.x;                      \
                    unsigned b1 = (nt & 1) ? b4.w : b4.y;                      \
                    mma16(acc[mt][nt], af[mt].x, af[mt].y, af[mt].z, af[mt].w, b0, b1); \
                }                                                              \
            }                                                                  \
        }                                                                      \
    }

// ---------------------------------------------------------------------------
// Out-projection GEMM: row-major fp32 C + bias.
// ---------------------------------------------------------------------------
__global__ __launch_bounds__(128, 2) void gemm_h(
    const unsigned* __restrict__ Ap, const unsigned* __restrict__ Bp,
    const float* __restrict__ bias, float* __restrict__ C,
    int M, int N, int K)
{
    extern __shared__ unsigned smg[];
    const int tid    = threadIdx.x;
    const int lane   = tid & 31;
    const int wid    = tid >> 5;
    const int warp_m = wid >> 1;
    const int warp_n = wid & 1;
    const int nKB    = K >> 5;

    GEMM_MAINLOOP(Ap, Bp, nKB)

    const int m0 = blockIdx.y * 128;
    const int n0 = blockIdx.x * 128;
#pragma unroll
    for (int mt = 0; mt < 4; mt++) {
        int row = m0 + warp_m * 64 + mt * 16 + (lane >> 2);
#pragma unroll
        for (int nt = 0; nt < 8; nt++) {
            int col = n0 + warp_n * 64 + nt * 8 + 2 * (lane & 3);
            float2 bv = *(const float2*)&bias[col];
            float2 o0 = make_float2(acc[mt][nt][0] + bv.x, acc[mt][nt][1] + bv.y);
            float2 o1 = make_float2(acc[mt][nt][2] + bv.x, acc[mt][nt][3] + bv.y);
            *(float2*)&C[(size_t)row * N + col]       = o0;
            *(float2*)&C[(size_t)(row + 8) * N + col] = o1;
        }
    }
}

// ---------------------------------------------------------------------------
// QKV GEMM with fused fp16 fragment-pack epilogue.
// Grid.x: 0-7 Q, 8-15 K, 16-23 V (128-col bands).
// ---------------------------------------------------------------------------
__global__ __launch_bounds__(128, 2) void gemm_qkv(
    const unsigned* __restrict__ Ap, const unsigned* __restrict__ Bp,
    const float* __restrict__ bias)
{
    extern __shared__ unsigned smg[];
    const int tid    = threadIdx.x;
    const int lane   = tid & 31;
    const int wid    = tid >> 5;
    const int warp_m = wid >> 1;
    const int warp_n = wid & 1;
    const int nKB    = Dc >> 5;

    GEMM_MAINLOOP(Ap, Bp, nKB)

    const int m0 = blockIdx.y * 128;
    const int n0 = blockIdx.x * 128;
    const int kind = n0 >> 10;    // 0=Q, 1=K, 2=V
    __half* gv = (__half*)g_vf;

#pragma unroll
    for (int mt = 0; mt < 4; mt++) {
        int row = m0 + warp_m * 64 + mt * 16 + (lane >> 2);
#pragma unroll
        for (int nt = 0; nt < 8; nt++) {
            int col = n0 + warp_n * 64 + nt * 8 + 2 * (lane & 3);
            float2 bv = *(const float2*)&bias[col];
            float v0 = acc[mt][nt][0] + bv.x, v1 = acc[mt][nt][1] + bv.y;
            float v2 = acc[mt][nt][2] + bv.x, v3 = acc[mt][nt][3] + bv.y;

            int s = row & (Sc - 1), b = row >> 11;
            int cc = col & 1023;
            int h = cc >> 6, d = cc & 63;           // d even
            int sl = s & 63;
            size_t base = ((size_t)(b * Hc + h) * 32 + (s >> 6)) * 2048;

            if (kind == 0) {
                float q0 = v0 * 0.125f, q1 = v1 * 0.125f;
                float q2 = v2 * 0.125f, q3 = v3 * 0.125f;
                int idx = (d >> 4) * 512 + ((sl >> 4) & 3) * 128
                        + (((sl & 7) << 2) | ((d >> 1) & 3)) * 4
                        + (((d >> 3) & 1) << 1);
                g_qfh[base + idx]     = h2(q0, q1);
                g_qfh[base + idx + 1] = h2(q2, q3);
                g_qfl[base + idx]     = h2(q0 - hi16(q0), q1 - hi16(q1));
                g_qfl[base + idx + 1] = h2(q2 - hi16(q2), q3 - hi16(q3));
            } else if (kind == 1) {
                int idx = (d >> 4) * 512 + ((sl >> 4) & 3) * 128
                        + (((sl & 7) << 2) | ((d >> 1) & 3)) * 4
                        + ((d >> 3) & 1);
                g_kfh[base + idx]     = h2(v0, v1);       // e=0 (row s)
                g_kfh[base + idx + 2] = h2(v2, v3);       // e=1 (row s+8)
                g_kfl[base + idx]     = h2(v0 - hi16(v0), v1 - hi16(v1));
                g_kfl[base + idx + 2] = h2(v2 - hi16(v2), v3 - hi16(v3));
            } else {
                float vv[4] = {v0, v1, v2, v3};
#pragma unroll
                for (int e = 0; e < 4; e++) {
                    int key = sl + (e >> 1) * 8;
                    int dim = d + (e & 1);
                    int widx = (key >> 4) * 512 + ((dim >> 4) & 3) * 128
                             + (((dim & 7) << 2) | ((key >> 1) & 3)) * 4
                             + ((((dim >> 3) & 1) << 1) | ((key >> 3) & 1));
                    gv[(base + widx) * 2 + (key & 1)] = __float2half_rn(vv[e]);
                }
            }
        }
    }
}

// ---------------------------------------------------------------------------
// fp16 tensor-core windowed attention (unchanged from R13, proven).
// ---------------------------------------------------------------------------
__global__ __launch_bounds__(128, 3) void attn_mma(unsigned* __restrict__ Operm)
{
    extern __shared__ unsigned sm[];
    const int tid = threadIdx.x, lane = tid & 31, wid = tid >> 5;
    const int qt = blockIdx.x, h = blockIdx.y, b = blockIdx.z;
    const int bh = b * Hc + h;
    const uint32_t sbase = (uint32_t)__cvta_generic_to_shared(sm);

    {
        const unsigned* qh_ = g_qfh + ((size_t)bh * 32 + qt) * 2048;
        const unsigned* ql_ = g_qfl + ((size_t)bh * 32 + qt) * 2048;
#pragma unroll
        for (int j = 0; j < 4; j++) {
            int c = tid + 128 * j;
            asm volatile("cp.async.cg.shared.global [%0],[%1],16;"
                         :: "r"(sbase + c * 16u), "l"(qh_ + c * 4));
            asm volatile("cp.async.cg.shared.global [%0],[%1],16;"
                         :: "r"(sbase + 8192u + c * 16u), "l"(ql_ + c * 4));
        }
        asm volatile("cp.async.commit_group;");
        asm volatile("cp.async.wait_group 0;");
    }
    __syncthreads();
    uint4 qh[4], ql[4];
#pragma unroll
    for (int ks = 0; ks < 4; ks++) {
        qh[ks] = *(const uint4*)&sm[ks * 512 + wid * 128 + lane * 4];
        ql[ks] = *(const uint4*)&sm[2048 + ks * 512 + wid * 128 + lane * 4];
    }
    __syncthreads();

    const int ktlo = (qt - 2 > 0) ? qt - 2 : 0;
    const int kthi = (qt + 2 < 31) ? qt + 2 : 31;
    const int nT = kthi - ktlo + 1;

#define ISSUE_KV(kt, p)                                                         \
    {                                                                           \
        const unsigned* kh_ = g_kfh + ((size_t)bh * 32 + (kt)) * 2048;          \
        const unsigned* kl_ = g_kfl + ((size_t)bh * 32 + (kt)) * 2048;          \
        const unsigned* v_  = g_vf  + ((size_t)bh * 32 + (kt)) * 2048;          \
        uint32_t dst = sbase + (p) * 24576u;                                    \
        _Pragma("unroll")                                                       \
        for (int j = 0; j < 4; j++) {                                           \
            int c = tid + 128 * j;                                              \
            asm volatile("cp.async.cg.shared.global [%0],[%1],16;"              \
                         :: "r"(dst + c * 16u), "l"(kh_ + c * 4));              \
            asm volatile("cp.async.cg.shared.global [%0],[%1],16;"              \
                         :: "r"(dst + 8192u + c * 16u), "l"(kl_ + c * 4));      \
            asm volatile("cp.async.cg.shared.global [%0],[%1],16;"              \
                         :: "r"(dst + 16384u + c * 16u), "l"(v_ + c * 4));      \
        }                                                                       \
        asm volatile("cp.async.commit_group;");                                 \
    }

    ISSUE_KV(ktlo, 0);
    ISSUE_KV(ktlo + 1, 1);

    float o[8][4];
#pragma unroll
    for (int i = 0; i < 8; i++)
#pragma unroll
        for (int c = 0; c < 4; c++) o[i][c] = 0.f;
    float mA = -1e30f, mB = -1e30f, lA = 0.f, lB = 0.f;

    for (int j = 0; j < nT; j++) {
        const int kt = ktlo + j, p = j & 1;
        asm volatile("cp.async.wait_group 1;");
        __syncthreads();

        const unsigned* bKh = sm + p * 6144;
        const unsigned* bKl = bKh + 2048;
        const unsigned* bV  = bKh + 4096;

        float s[8][4];
#pragma unroll
        for (int i = 0; i < 8; i++)
#pragma unroll
            for (int c = 0; c < 4; c++) s[i][c] = 0.f;

#pragma unroll
        for (int ks = 0; ks < 4; ks++) {
            uint4 kh4[4], kl4[4];
#pragma unroll
            for (int ntp = 0; ntp < 4; ntp++) {
                kh4[ntp] = *(const uint4*)&bKh[ks * 512 + ntp * 128 + lane * 4];
                kl4[ntp] = *(const uint4*)&bKl[ks * 512 + ntp * 128 + lane * 4];
            }
#pragma unroll
            for (int ntp = 0; ntp < 4; ntp++) {
#pragma unroll
                for (int e = 0; e < 2; e++) {
                    unsigned bh0 = e ? kh4[ntp].z : kh4[ntp].x;
                    unsigned bh1 = e ? kh4[ntp].w : kh4[ntp].y;
                    unsigned bl0 = e ? kl4[ntp].z : kl4[ntp].x;
                    unsigned bl1 = e ? kl4[ntp].w : kl4[ntp].y;
                    float* c = s[ntp * 2 + e];
                    mma16(c, qh[ks].x, qh[ks].y, qh[ks].z, qh[ks].w, bh0, bh1);
                    mma16(c, ql[ks].x, ql[ks].y, ql[ks].z, ql[ks].w, bh0, bh1);
                    mma16(c, qh[ks].x, qh[ks].y, qh[ks].z, qh[ks].w, bl0, bl1);
                }
            }
        }

        if (kt - qt == 2 || qt - kt == 2) {
            int q1 = qt * 64 + wid * 16 + (lane >> 2);
            int k00 = kt * 64 + 2 * (lane & 3);
#pragma unroll
            for (int nt = 0; nt < 8; nt++) {
#pragma unroll
                for (int ci = 0; ci < 4; ci++) {
                    int qv = q1 + ((ci >= 2) ? 8 : 0);
                    int kv = k00 + nt * 8 + (ci & 1);
                    int d = qv - kv; d = (d < 0) ? -d : d;
                    if (d > Wc) s[nt][ci] = -1e30f;
                }
            }
        }

        float tA = -1e30f, tB = -1e30f;
#pragma unroll
        for (int nt = 0; nt < 8; nt++) {
            tA = fmaxf(tA, fmaxf(s[nt][0], s[nt][1]));
            tB = fmaxf(tB, fmaxf(s[nt][2], s[nt][3]));
        }
        tA = fmaxf(tA, __shfl_xor_sync(0xffffffffu, tA, 1));
        tA = fmaxf(tA, __shfl_xor_sync(0xffffffffu, tA, 2));
        tB = fmaxf(tB, __shfl_xor_sync(0xffffffffu, tB, 1));
        tB = fmaxf(tB, __shfl_xor_sync(0xffffffffu, tB, 2));
        float mnA = fmaxf(mA, tA), mnB = fmaxf(mB, tB);
        float aA = __expf(mA - mnA), aB = __expf(mB - mnB);
        mA = mnA; mB = mnB;
        float sumA = 0.f, sumB = 0.f;
#pragma unroll
        for (int nt = 0; nt < 8; nt++) {
            s[nt][0] = __expf(s[nt][0] - mnA);
            s[nt][1] = __expf(s[nt][1] - mnA);
            s[nt][2] = __expf(s[nt][2] - mnB);
            s[nt][3] = __expf(s[nt][3] - mnB);
            sumA += s[nt][0] + s[nt][1];
            sumB += s[nt][2] + s[nt][3];
        }
        sumA += __shfl_xor_sync(0xffffffffu, sumA, 1);
        sumA += __shfl_xor_sync(0xffffffffu, sumA, 2);
        sumB += __shfl_xor_sync(0xffffffffu, sumB, 1);
        sumB += __shfl_xor_sync(0xffffffffu, sumB, 2);
        lA = lA * aA + sumA;
        lB = lB * aB + sumB;
#pragma unroll
        for (int nt = 0; nt < 8; nt++) {
            o[nt][0] *= aA; o[nt][1] *= aA;
            o[nt][2] *= aB; o[nt][3] *= aB;
        }

#pragma unroll
        for (int kk = 0; kk < 4; kk++) {
            unsigned pa0 = h2(s[2 * kk][0],     s[2 * kk][1]);
            unsigned pa1 = h2(s[2 * kk][2],     s[2 * kk][3]);
            unsigned pa2 = h2(s[2 * kk + 1][0], s[2 * kk + 1][1]);
            unsigned pa3 = h2(s[2 * kk + 1][2], s[2 * kk + 1][3]);
            uint4 v4[4];
#pragma unroll
            for (int ntp = 0; ntp < 4; ntp++)
                v4[ntp] = *(const uint4*)&bV[kk * 512 + ntp * 128 + lane * 4];
#pragma unroll
            for (int ntp = 0; ntp < 4; ntp++) {
#pragma unroll
                for (int e = 0; e < 2; e++) {
                    unsigned b0 = e ? v4[ntp].z : v4[ntp].x;
                    unsigned b1 = e ? v4[ntp].w : v4[ntp].y;
                    mma16(o[ntp * 2 + e], pa0, pa1, pa2, pa3, b0, b1);
                }
            }
        }
        __syncthreads();

        if (kt + 2 <= kthi) {
            ISSUE_KV(kt + 2, p);
        } else {
            asm volatile("cp.async.commit_group;");
        }
    }

    float iA = 1.f / lA, iB = 1.f / lB;
    int q = b * Sc + qt * 64 + wid * 16 + (lane >> 2);
    int mblk = q >> 7, mtg = (q >> 4) & 7;
#pragma unroll
    for (int nt = 0; nt < 8; nt++) {
        int c0 = h * 64 + nt * 8 + 2 * (lane & 3);
        int kblk = c0 >> 5;
        int kstep = (c0 >> 4) & 1;
        int lanep = ((q & 7) << 2) | ((c0 >> 1) & 3);
        int slotb = ((c0 >> 3) & 1) << 1;
        size_t bidx = (size_t)(mblk * 32 + kblk) * 2048 + kstep * 1024
                    + mtg * 128 + lanep * 4 + slotb;
        Operm[bidx]     = h2(o[nt][0] * iA, o[nt][1] * iA);
        Operm[bidx + 1] = h2(o[nt][2] * iB, o[nt][3] * iB);
    }
#undef ISSUE_KV
}

// ---------------------------------------------------------------------------
extern "C" void kernel_launch(void* const* d_in, const int* in_sizes, int n_in,
                              void* d_out, int out_size)
{
    (void)in_sizes; (void)n_in; (void)out_size;
    const float* x     = (const float*)d_in[0];
    const float* in_w  = (const float*)d_in[1];
    const float* in_b  = (const float*)d_in[2];
    const float* out_w = (const float*)d_in[3];
    const float* out_b = (const float*)d_in[4];
    float* out = (float*)d_out;

    unsigned *xp, *ap, *wqp, *wop;
    cudaGetSymbolAddress((void**)&xp,  g_xperm);
    cudaGetSymbolAddress((void**)&ap,  g_attnperm);
    cudaGetSymbolAddress((void**)&wqp, g_wqkvperm);
    cudaGetSymbolAddress((void**)&wop, g_woutperm);

    const int M = Bc * Sc;                      // 4096
    const int smem_gemm = GSTAGES * 16384;      // 80 KB -> 2 CTAs/SM
    const int smem_attn = 12288 * 4;            // 48 KB -> 3 CTAs/SM
    cudaFuncSetAttribute(gemm_h,
                         cudaFuncAttributeMaxDynamicSharedMemorySize, smem_gemm);
    cudaFuncSetAttribute(gemm_qkv,
                         cudaFuncAttributeMaxDynamicSharedMemorySize, smem_gemm);
    cudaFuncSetAttribute(attn_mma,
                         cudaFuncAttributeMaxDynamicSharedMemorySize, smem_attn);

    // Operand packers (fp16)
    permA_h<<<(M * Dc / 2 + 255) / 256, 256>>>(x, xp, M, Dc);
    permB_h<<<(3 * Dc * Dc / 2 + 255) / 256, 256>>>(in_w, wqp, 3 * Dc, Dc);
    permB_h<<<(Dc * Dc / 2 + 255) / 256, 256>>>(out_w, wop, Dc, Dc);

    // 1) QKV projection with fused Q/K/V fragment-pack epilogue
    gemm_qkv<<<dim3(3 * Dc / 128, M / 128), 128, smem_gemm>>>(xp, wqp, in_b);

    // 2) fp16 tensor-core attention (writes out-proj A-fragments directly)
    attn_mma<<<dim3(Sc / 64, Hc, Bc), 128, smem_attn>>>(ap);

    // 3) Output projection
    gemm_h<<<dim3(Dc / 128, M / 128), 128, smem_gemm>>>(
        ap, wop, out_b, out, M, Dc, Dc);
}